// round 10
// baseline (speedup 1.0000x reference)
#include <cuda_runtime.h>
#include <cstdint>

#define GRID_G   180
#define NV       (GRID_G * GRID_G)            // 32400
#define CELLS    (179 * 179)                  // 32041
#define NF_BASE  (2 * CELLS)                  // 64082 faces
#define B0       (3 * CELLS)                  // 96123
#define NUM_NEW  (B0 + 358)                   // 96481
#define DIM      256
#define BATCH    4
#define ROWS_OUT (NV + NUM_NEW)               // 128881
#define NFACES4  (4 * NF_BASE)                // 256328
#define NEDGE    (12 * NF_BASE)               // 768984

#define OUT_FEAT_ELEMS   ((size_t)BATCH * ROWS_OUT * DIM)      // 131,974,144
#define OUT_NF_ELEMS     ((size_t)BATCH * NFACES4 * 3)         // 3,075,936

#define PER_B_OUT4   (ROWS_OUT * 64)                           // out float4 per batch
#define PER_B_IN4    (NV * 64)                                 // 2,073,600 x float4/batch
#define GATHER_B4    (NUM_NEW * 64)                            // 6,174,784 per batch

// Interleaved schedule, period 7: [Copy(4-slot), G, G, G, G, G, G].
// Copy: 4 float4/thread -> 1024 slots/block -> 2025 blocks/batch (exact).
// Gather: 2 float4 slots/thread -> 12061 needed <= 2025*6 = 12150 (tail-guarded).
#define CPB          2025
#define BPB          (CPB * 7)                                 // 14175 blocks per batch
#define TOPO_BPB     ((NF_BASE + 255) / 256)                   // 251
#define TOPO_BLOCKS  (TOPO_BPB * BATCH)                        // 1004
#define TOTAL_BLOCKS (TOPO_BLOCKS + BATCH * BPB)               // 57704

// Analytic endpoints of the j-th new edge (first-occurrence order).
__device__ __forceinline__ void edge_endpoints(int j, int& p0, int& p1) {
    if (j < B0) {
        int q = j / 3;
        int t = j - q * 3;
        int r = q / 179;
        int cc = q - r * 179;
        int v00 = r * GRID_G + cc;
        if (t == 0)      { p0 = v00;       p1 = v00 + 1;   }      // H(r,cc)
        else if (t == 1) { p0 = v00 + 1;   p1 = v00 + 181; }      // V(r,cc+1)
        else             { p0 = v00;       p1 = v00 + 181; }      // D(r,cc)
    } else {
        int m = j - B0;
        if (m <= 177)      { p0 = m * GRID_G;       p1 = (m + 1) * GRID_G; }     // V(m,0)
        else if (m == 178) { p0 = 179 * GRID_G;     p1 = 179 * GRID_G + 1; }     // H(179,0)
        else if (m == 179) { p0 = 178 * GRID_G;     p1 = 179 * GRID_G;     }     // V(178,0)
        else { int cc = m - 179; p0 = 179 * GRID_G + cc; p1 = p0 + 1; }          // H(179,cc)
    }
}

__device__ __forceinline__ void topo_face(float* __restrict__ out, int f, int b) {
    int v0, v1, v2, n0, n1, n2;
    if (f < CELLS) {
        int c = f;
        int r = c / 179, cc = c - r * 179;
        int v00 = r * GRID_G + cc;
        v0 = v00; v1 = v00 + 1; v2 = v00 + 181;
        n0 = NV + 3 * c;        // H(r,cc)
        n1 = NV + 3 * c + 1;    // V(r,cc+1)
        n2 = NV + 3 * c + 2;    // D(r,cc)
    } else {
        int c = f - CELLS;
        int r = c / 179, cc = c - r * 179;
        int v00 = r * GRID_G + cc;
        v0 = v00; v1 = v00 + 181; v2 = v00 + 180;
        n0 = NV + 3 * c + 2;    // D(r,cc)
        if (r < 178) n1 = NV + 3 * ((r + 1) * 179 + cc);
        else         n1 = (cc == 0) ? (NV + B0 + 178) : (NV + B0 + 179 + cc);
        if (cc >= 1) n2 = NV + 3 * (r * 179 + cc - 1) + 1;
        else         n2 = (r <= 177) ? (NV + B0 + r) : (NV + B0 + 179);
    }

    float* nf  = out + OUT_FEAT_ELEMS + (size_t)b * NFACES4 * 3;
    float* ne0 = out + OUT_FEAT_ELEMS + OUT_NF_ELEMS + (size_t)b * 2 * NEDGE;
    float* ne1 = ne0 + NEDGE;

    int ta[4] = { v0, n0, n1, n0 };
    int tb[4] = { n0, v1, v2, n1 };
    int tc[4] = { n2, n1, n2, n2 };
    int rows[4] = { f, NF_BASE + f, 2 * NF_BASE + f, 3 * NF_BASE + f };

#pragma unroll
    for (int k = 0; k < 4; k++) {
        int g = rows[k];
        float A = (float)ta[k], Bv = (float)tb[k], Cv = (float)tc[k];
        __stcs(&nf[3 * g],     A);
        __stcs(&nf[3 * g + 1], Bv);
        __stcs(&nf[3 * g + 2], Cv);
        __stcs(&ne0[g],               A);
        __stcs(&ne0[4 * NF_BASE + g], Bv);
        __stcs(&ne0[8 * NF_BASE + g], Cv);
        __stcs(&ne1[g],               Bv);
        __stcs(&ne1[4 * NF_BASE + g], Cv);
        __stcs(&ne1[8 * NF_BASE + g], A);
    }
}

// Schedule: [topo | per batch: (C G G G G G G) x 2025]. Copy and gather
// frontiers advance over the same mesh region in lockstep, so gather reads
// hit lines copy just staged in L2. Both paths front-batch their loads.
__global__ void __launch_bounds__(256) fused_kernel(const float4* __restrict__ x,
                                                    float* __restrict__ out) {
    unsigned bx = blockIdx.x;
    if (bx < TOPO_BLOCKS) {
        int b = bx / TOPO_BPB;
        int f = (bx - b * TOPO_BPB) * 256 + threadIdx.x;
        if (f < NF_BASE) topo_face(out, f, b);
        return;
    }
    int t = bx - TOPO_BLOCKS;
    int b = t / BPB;
    int r = t - b * BPB;
    const float4* xb = x + (size_t)b * PER_B_IN4;
    float4* ob = (float4*)out + (size_t)b * PER_B_OUT4;

    int quot = r / 7;
    int m    = r - quot * 7;
    if (m == 0) {
        // Copy block: 1024 consecutive float4 slots, 4 loads in flight.
        int s0 = quot * 1024 + threadIdx.x;
        float4 v0 = __ldcg(&xb[s0]);
        float4 v1 = __ldcg(&xb[s0 + 256]);
        float4 v2 = __ldcg(&xb[s0 + 512]);
        float4 v3 = __ldcg(&xb[s0 + 768]);
        __stcs(&ob[s0],       v0);
        __stcs(&ob[s0 + 256], v1);
        __stcs(&ob[s0 + 512], v2);
        __stcs(&ob[s0 + 768], v3);
    } else {
        // Gather block: 2 slots, ALL 4 endpoint loads front-batched before
        // any store. Guards via clamp + predicated store (no branch between
        // the loads, so ptxas emits one straight-line load pack).
        int g  = quot * 6 + (m - 1);          // 0..12149 (>=12061 tail)
        int s  = g * 512 + threadIdx.x;
        int sA = s;
        int sB = s + 256;
        bool vA = (sA < GATHER_B4);
        bool vB = (sB < GATHER_B4);
        int cA = vA ? sA : 0;
        int cB = vB ? sB : 0;

        int jA = cA >> 6, qA = cA & 63;
        int jB = cB >> 6, qB = cB & 63;
        int pA0, pA1, pB0, pB1;
        edge_endpoints(jA, pA0, pA1);
        edge_endpoints(jB, pB0, pB1);

        float4 a0 = __ldg(&xb[pA0 * 64 + qA]);
        float4 c0 = __ldg(&xb[pA1 * 64 + qA]);
        float4 a1 = __ldg(&xb[pB0 * 64 + qB]);
        float4 c1 = __ldg(&xb[pB1 * 64 + qB]);

        if (vA) {
            float4 r4;
            r4.x = 0.5f * (a0.x + c0.x);
            r4.y = 0.5f * (a0.y + c0.y);
            r4.z = 0.5f * (a0.z + c0.z);
            r4.w = 0.5f * (a0.w + c0.w);
            __stcs(&ob[(NV + jA) * 64 + qA], r4);
        }
        if (vB) {
            float4 r4;
            r4.x = 0.5f * (a1.x + c1.x);
            r4.y = 0.5f * (a1.y + c1.y);
            r4.z = 0.5f * (a1.z + c1.z);
            r4.w = 0.5f * (a1.w + c1.w);
            __stcs(&ob[(NV + jB) * 64 + qB], r4);
        }
    }
}

extern "C" void kernel_launch(void* const* d_in, const int* in_sizes, int n_in,
                              void* d_out, int out_size) {
    const float4* x = (const float4*)d_in[0];   // x (4, 32400, 256) f32
    float* out = (float*)d_out;
    fused_kernel<<<TOTAL_BLOCKS, 256>>>(x, out);
}

// round 12
// speedup vs baseline: 1.0131x; 1.0131x over previous
#include <cuda_runtime.h>
#include <cstdint>

#define GRID_G   180
#define NV       (GRID_G * GRID_G)            // 32400
#define CELLS    (179 * 179)                  // 32041
#define NF_BASE  (2 * CELLS)                  // 64082 faces
#define B0       (3 * CELLS)                  // 96123
#define NUM_NEW  (B0 + 358)                   // 96481
#define DIM      256
#define BATCH    4
#define ROWS_OUT (NV + NUM_NEW)               // 128881
#define NFACES4  (4 * NF_BASE)                // 256328
#define NEDGE    (12 * NF_BASE)               // 768984

#define OUT_FEAT_ELEMS   ((size_t)BATCH * ROWS_OUT * DIM)      // 131,974,144
#define OUT_NF_ELEMS     ((size_t)BATCH * NFACES4 * 3)         // 3,075,936

#define PER_B_OUT4   (ROWS_OUT * 64)                           // out float4 per batch
#define PER_B_IN4    (NV * 64)                                 // 2,073,600 x float4/batch
#define GATHER_B4    (NUM_NEW * 64)                            // 6,174,784 per batch

// Interleaved schedule, period 7: [Copy(4-slot), G, G, G, G, G, G].
// Copy: 4 float4/thread -> 1024 slots/block -> 2025 blocks/batch (exact).
// Gather: 2 float4 slots/thread -> 12061 needed <= 2025*6 = 12150 (tail-guarded).
#define CPB          2025
#define BPB          (CPB * 7)                                 // 14175 blocks per batch
#define TOPO_BPB     ((NF_BASE + 255) / 256)                   // 251
#define TOPO_BLOCKS  (TOPO_BPB * BATCH)                        // 1004
#define TOTAL_BLOCKS (TOPO_BLOCKS + BATCH * BPB)               // 57704

// Analytic endpoints of the j-th new edge (first-occurrence order).
__device__ __forceinline__ void edge_endpoints(int j, int& p0, int& p1) {
    if (j < B0) {
        int q = j / 3;
        int t = j - q * 3;
        int r = q / 179;
        int cc = q - r * 179;
        int v00 = r * GRID_G + cc;
        if (t == 0)      { p0 = v00;       p1 = v00 + 1;   }      // H(r,cc)
        else if (t == 1) { p0 = v00 + 1;   p1 = v00 + 181; }      // V(r,cc+1)
        else             { p0 = v00;       p1 = v00 + 181; }      // D(r,cc)
    } else {
        int m = j - B0;
        if (m <= 177)      { p0 = m * GRID_G;       p1 = (m + 1) * GRID_G; }     // V(m,0)
        else if (m == 178) { p0 = 179 * GRID_G;     p1 = 179 * GRID_G + 1; }     // H(179,0)
        else if (m == 179) { p0 = 178 * GRID_G;     p1 = 179 * GRID_G;     }     // V(178,0)
        else { int cc = m - 179; p0 = 179 * GRID_G + cc; p1 = p0 + 1; }          // H(179,cc)
    }
}

// mean of two float4 via packed f32x2 (half the scalar-op count of 0.5*(a+c);
// add.rn/mul.rn per lane -> bit-identical to the scalar expression).
__device__ __forceinline__ float4 mean4(float4 a, float4 c) {
    unsigned long long a0, a1, c0, c1, s0, s1;
    const unsigned long long h2 = 0x3F0000003F000000ULL;   // {0.5f, 0.5f}
    asm("mov.b64 %0, {%1, %2};" : "=l"(a0) : "f"(a.x), "f"(a.y));
    asm("mov.b64 %0, {%1, %2};" : "=l"(a1) : "f"(a.z), "f"(a.w));
    asm("mov.b64 %0, {%1, %2};" : "=l"(c0) : "f"(c.x), "f"(c.y));
    asm("mov.b64 %0, {%1, %2};" : "=l"(c1) : "f"(c.z), "f"(c.w));
    asm("add.rn.f32x2 %0, %1, %2;" : "=l"(s0) : "l"(a0), "l"(c0));
    asm("add.rn.f32x2 %0, %1, %2;" : "=l"(s1) : "l"(a1), "l"(c1));
    asm("mul.rn.f32x2 %0, %1, %2;" : "=l"(s0) : "l"(s0), "l"(h2));
    asm("mul.rn.f32x2 %0, %1, %2;" : "=l"(s1) : "l"(s1), "l"(h2));
    float4 r;
    asm("mov.b64 {%0, %1}, %2;" : "=f"(r.x), "=f"(r.y) : "l"(s0));
    asm("mov.b64 {%0, %1}, %2;" : "=f"(r.z), "=f"(r.w) : "l"(s1));
    return r;
}

__device__ __forceinline__ void gather_slot(const float4* __restrict__ xb,
                                            float4* __restrict__ ob, int s) {
    int j = s >> 6;
    int q = s & 63;
    int p0, p1;
    edge_endpoints(j, p0, p1);
    float4 a = __ldg(&xb[p0 * 64 + q]);
    float4 c = __ldg(&xb[p1 * 64 + q]);
    __stcs(&ob[(NV + j) * 64 + q], mean4(a, c));
}

__device__ __forceinline__ void topo_face(float* __restrict__ out, int f, int b) {
    int v0, v1, v2, n0, n1, n2;
    if (f < CELLS) {
        int c = f;
        int r = c / 179, cc = c - r * 179;
        int v00 = r * GRID_G + cc;
        v0 = v00; v1 = v00 + 1; v2 = v00 + 181;
        n0 = NV + 3 * c;        // H(r,cc)
        n1 = NV + 3 * c + 1;    // V(r,cc+1)
        n2 = NV + 3 * c + 2;    // D(r,cc)
    } else {
        int c = f - CELLS;
        int r = c / 179, cc = c - r * 179;
        int v00 = r * GRID_G + cc;
        v0 = v00; v1 = v00 + 181; v2 = v00 + 180;
        n0 = NV + 3 * c + 2;    // D(r,cc)
        if (r < 178) n1 = NV + 3 * ((r + 1) * 179 + cc);
        else         n1 = (cc == 0) ? (NV + B0 + 178) : (NV + B0 + 179 + cc);
        if (cc >= 1) n2 = NV + 3 * (r * 179 + cc - 1) + 1;
        else         n2 = (r <= 177) ? (NV + B0 + r) : (NV + B0 + 179);
    }

    float* nf  = out + OUT_FEAT_ELEMS + (size_t)b * NFACES4 * 3;
    float* ne0 = out + OUT_FEAT_ELEMS + OUT_NF_ELEMS + (size_t)b * 2 * NEDGE;
    float* ne1 = ne0 + NEDGE;

    int ta[4] = { v0, n0, n1, n0 };
    int tb[4] = { n0, v1, v2, n1 };
    int tc[4] = { n2, n1, n2, n2 };
    int rows[4] = { f, NF_BASE + f, 2 * NF_BASE + f, 3 * NF_BASE + f };

#pragma unroll
    for (int k = 0; k < 4; k++) {
        int g = rows[k];
        float A = (float)ta[k], Bv = (float)tb[k], Cv = (float)tc[k];
        __stcs(&nf[3 * g],     A);
        __stcs(&nf[3 * g + 1], Bv);
        __stcs(&nf[3 * g + 2], Cv);
        __stcs(&ne0[g],               A);
        __stcs(&ne0[4 * NF_BASE + g], Bv);
        __stcs(&ne0[8 * NF_BASE + g], Cv);
        __stcs(&ne1[g],               Bv);
        __stcs(&ne1[4 * NF_BASE + g], Cv);
        __stcs(&ne1[8 * NF_BASE + g], A);
    }
}

// Schedule: [topo | per batch: (C G G G G G G) x 2025]. Copy and gather
// frontiers advance over the same mesh region in lockstep, so gather reads
// hit lines copy just staged in L2; DRAM sees a steady ~1:4 read:write mix.
__global__ void __launch_bounds__(256) fused_kernel(const float4* __restrict__ x,
                                                    float* __restrict__ out) {
    unsigned bx = blockIdx.x;
    if (bx < TOPO_BLOCKS) {
        int b = bx / TOPO_BPB;
        int f = (bx - b * TOPO_BPB) * 256 + threadIdx.x;
        if (f < NF_BASE) topo_face(out, f, b);
        return;
    }
    int t = bx - TOPO_BLOCKS;
    int b = t / BPB;
    int r = t - b * BPB;
    const float4* xb = x + (size_t)b * PER_B_IN4;
    float4* ob = (float4*)out + (size_t)b * PER_B_OUT4;

    int quot = r / 7;
    int m    = r - quot * 7;
    if (m == 0) {
        // Copy block: 1024 consecutive float4 slots, 4 loads in flight per
        // thread before any store (deep DRAM-read MLP, register-cheap).
        int s0 = quot * 1024 + threadIdx.x;
        float4 v0 = __ldcg(&xb[s0]);
        float4 v1 = __ldcg(&xb[s0 + 256]);
        float4 v2 = __ldcg(&xb[s0 + 512]);
        float4 v3 = __ldcg(&xb[s0 + 768]);
        __stcs(&ob[s0],       v0);
        __stcs(&ob[s0 + 256], v1);
        __stcs(&ob[s0 + 512], v2);
        __stcs(&ob[s0 + 768], v3);
    } else {
        int g = quot * 6 + (m - 1);          // 0..12149 (>=12061 tail-guarded)
        int s = g * 512 + threadIdx.x;
        if (s < GATHER_B4) gather_slot(xb, ob, s);
        int s2 = s + 256;
        if (s2 < GATHER_B4) gather_slot(xb, ob, s2);
    }
}

extern "C" void kernel_launch(void* const* d_in, const int* in_sizes, int n_in,
                              void* d_out, int out_size) {
    const float4* x = (const float4*)d_in[0];   // x (4, 32400, 256) f32
    float* out = (float*)d_out;
    fused_kernel<<<TOTAL_BLOCKS, 256>>>(x, out);
}

// round 13
// speedup vs baseline: 1.0435x; 1.0300x over previous
#include <cuda_runtime.h>
#include <cstdint>

#define GRID_G   180
#define NV       (GRID_G * GRID_G)            // 32400
#define CELLS    (179 * 179)                  // 32041
#define NF_BASE  (2 * CELLS)                  // 64082 faces
#define B0       (3 * CELLS)                  // 96123
#define NUM_NEW  (B0 + 358)                   // 96481
#define DIM      256
#define BATCH    4
#define ROWS_OUT (NV + NUM_NEW)               // 128881
#define NFACES4  (4 * NF_BASE)                // 256328
#define NEDGE    (12 * NF_BASE)               // 768984

#define OUT_FEAT_ELEMS   ((size_t)BATCH * ROWS_OUT * DIM)      // 131,974,144
#define OUT_NF_ELEMS     ((size_t)BATCH * NFACES4 * 3)         // 3,075,936

#define PER_B_OUT4   (ROWS_OUT * 64)                           // out float4 per batch
#define PER_B_IN4    (NV * 64)                                 // 2,073,600 x float4/batch
#define GATHER_B4    (NUM_NEW * 64)                            // 6,174,784 per batch

// Interleaved schedule, period 5: [Copy(4-slot), G, G, G, G] with 3-slot gather.
// Copy: 4 float4/thread -> 1024 slots/block -> 2025 blocks/batch (exact).
// Gather: 3 float4 slots/thread (768/block) -> 8041 needed <= 2025*4 = 8100.
// Byte ratio per period: 1024 copy : 3072 gather = identical fractions of
// their totals -> copy/gather L2 frontiers stay in lockstep.
#define CPB          2025
#define BPB          (CPB * 5)                                 // 10125 blocks per batch
#define TOPO_BPB     ((NF_BASE + 255) / 256)                   // 251
#define TOPO_BLOCKS  (TOPO_BPB * BATCH)                        // 1004
#define TOTAL_BLOCKS (TOPO_BLOCKS + BATCH * BPB)               // 41504

// Analytic endpoints of the j-th new edge (first-occurrence order).
__device__ __forceinline__ void edge_endpoints(int j, int& p0, int& p1) {
    if (j < B0) {
        int q = j / 3;
        int t = j - q * 3;
        int r = q / 179;
        int cc = q - r * 179;
        int v00 = r * GRID_G + cc;
        if (t == 0)      { p0 = v00;       p1 = v00 + 1;   }      // H(r,cc)
        else if (t == 1) { p0 = v00 + 1;   p1 = v00 + 181; }      // V(r,cc+1)
        else             { p0 = v00;       p1 = v00 + 181; }      // D(r,cc)
    } else {
        int m = j - B0;
        if (m <= 177)      { p0 = m * GRID_G;       p1 = (m + 1) * GRID_G; }     // V(m,0)
        else if (m == 178) { p0 = 179 * GRID_G;     p1 = 179 * GRID_G + 1; }     // H(179,0)
        else if (m == 179) { p0 = 178 * GRID_G;     p1 = 179 * GRID_G;     }     // V(178,0)
        else { int cc = m - 179; p0 = 179 * GRID_G + cc; p1 = p0 + 1; }          // H(179,cc)
    }
}

// mean of two float4 via packed f32x2 (half the scalar-op count of 0.5*(a+c);
// add.rn/mul.rn per lane -> bit-identical to the scalar expression).
__device__ __forceinline__ float4 mean4(float4 a, float4 c) {
    unsigned long long a0, a1, c0, c1, s0, s1;
    const unsigned long long h2 = 0x3F0000003F000000ULL;   // {0.5f, 0.5f}
    asm("mov.b64 %0, {%1, %2};" : "=l"(a0) : "f"(a.x), "f"(a.y));
    asm("mov.b64 %0, {%1, %2};" : "=l"(a1) : "f"(a.z), "f"(a.w));
    asm("mov.b64 %0, {%1, %2};" : "=l"(c0) : "f"(c.x), "f"(c.y));
    asm("mov.b64 %0, {%1, %2};" : "=l"(c1) : "f"(c.z), "f"(c.w));
    asm("add.rn.f32x2 %0, %1, %2;" : "=l"(s0) : "l"(a0), "l"(c0));
    asm("add.rn.f32x2 %0, %1, %2;" : "=l"(s1) : "l"(a1), "l"(c1));
    asm("mul.rn.f32x2 %0, %1, %2;" : "=l"(s0) : "l"(s0), "l"(h2));
    asm("mul.rn.f32x2 %0, %1, %2;" : "=l"(s1) : "l"(s1), "l"(h2));
    float4 r;
    asm("mov.b64 {%0, %1}, %2;" : "=f"(r.x), "=f"(r.y) : "l"(s0));
    asm("mov.b64 {%0, %1}, %2;" : "=f"(r.z), "=f"(r.w) : "l"(s1));
    return r;
}

__device__ __forceinline__ void gather_slot(const float4* __restrict__ xb,
                                            float4* __restrict__ ob, int s) {
    int j = s >> 6;
    int q = s & 63;
    int p0, p1;
    edge_endpoints(j, p0, p1);
    float4 a = __ldg(&xb[p0 * 64 + q]);
    float4 c = __ldg(&xb[p1 * 64 + q]);
    __stcs(&ob[(NV + j) * 64 + q], mean4(a, c));
}

__device__ __forceinline__ void topo_face(float* __restrict__ out, int f, int b) {
    int v0, v1, v2, n0, n1, n2;
    if (f < CELLS) {
        int c = f;
        int r = c / 179, cc = c - r * 179;
        int v00 = r * GRID_G + cc;
        v0 = v00; v1 = v00 + 1; v2 = v00 + 181;
        n0 = NV + 3 * c;        // H(r,cc)
        n1 = NV + 3 * c + 1;    // V(r,cc+1)
        n2 = NV + 3 * c + 2;    // D(r,cc)
    } else {
        int c = f - CELLS;
        int r = c / 179, cc = c - r * 179;
        int v00 = r * GRID_G + cc;
        v0 = v00; v1 = v00 + 181; v2 = v00 + 180;
        n0 = NV + 3 * c + 2;    // D(r,cc)
        if (r < 178) n1 = NV + 3 * ((r + 1) * 179 + cc);
        else         n1 = (cc == 0) ? (NV + B0 + 178) : (NV + B0 + 179 + cc);
        if (cc >= 1) n2 = NV + 3 * (r * 179 + cc - 1) + 1;
        else         n2 = (r <= 177) ? (NV + B0 + r) : (NV + B0 + 179);
    }

    float* nf  = out + OUT_FEAT_ELEMS + (size_t)b * NFACES4 * 3;
    float* ne0 = out + OUT_FEAT_ELEMS + OUT_NF_ELEMS + (size_t)b * 2 * NEDGE;
    float* ne1 = ne0 + NEDGE;

    int ta[4] = { v0, n0, n1, n0 };
    int tb[4] = { n0, v1, v2, n1 };
    int tc[4] = { n2, n1, n2, n2 };
    int rows[4] = { f, NF_BASE + f, 2 * NF_BASE + f, 3 * NF_BASE + f };

#pragma unroll
    for (int k = 0; k < 4; k++) {
        int g = rows[k];
        float A = (float)ta[k], Bv = (float)tb[k], Cv = (float)tc[k];
        __stcs(&nf[3 * g],     A);
        __stcs(&nf[3 * g + 1], Bv);
        __stcs(&nf[3 * g + 2], Cv);
        __stcs(&ne0[g],               A);
        __stcs(&ne0[4 * NF_BASE + g], Bv);
        __stcs(&ne0[8 * NF_BASE + g], Cv);
        __stcs(&ne1[g],               Bv);
        __stcs(&ne1[4 * NF_BASE + g], Cv);
        __stcs(&ne1[8 * NF_BASE + g], A);
    }
}

// Schedule: [topo | per batch: (C G G G G) x 2025]. Copy and gather frontiers
// advance over the same mesh region in lockstep, so gather reads hit lines
// copy just staged in L2; DRAM sees a steady ~1:4 read:write mix.
__global__ void __launch_bounds__(256) fused_kernel(const float4* __restrict__ x,
                                                    float* __restrict__ out) {
    unsigned bx = blockIdx.x;
    if (bx < TOPO_BLOCKS) {
        int b = bx / TOPO_BPB;
        int f = (bx - b * TOPO_BPB) * 256 + threadIdx.x;
        if (f < NF_BASE) topo_face(out, f, b);
        return;
    }
    int t = bx - TOPO_BLOCKS;
    int b = t / BPB;
    int r = t - b * BPB;
    const float4* xb = x + (size_t)b * PER_B_IN4;
    float4* ob = (float4*)out + (size_t)b * PER_B_OUT4;

    int quot = r / 5;
    int m    = r - quot * 5;
    if (m == 0) {
        // Copy block: 1024 consecutive float4 slots, 4 loads in flight per
        // thread before any store (deep DRAM-read MLP, register-cheap).
        int s0 = quot * 1024 + threadIdx.x;
        float4 v0 = __ldcg(&xb[s0]);
        float4 v1 = __ldcg(&xb[s0 + 256]);
        float4 v2 = __ldcg(&xb[s0 + 512]);
        float4 v3 = __ldcg(&xb[s0 + 768]);
        __stcs(&ob[s0],       v0);
        __stcs(&ob[s0 + 256], v1);
        __stcs(&ob[s0 + 512], v2);
        __stcs(&ob[s0 + 768], v3);
    } else {
        // Gather block: 3 serial slots (768 slots/block), tail-guarded.
        int g = quot * 4 + (m - 1);          // 0..8099 (>=8041 tail-guarded)
        int s = g * 768 + threadIdx.x;
        if (s < GATHER_B4) gather_slot(xb, ob, s);
        int s2 = s + 256;
        if (s2 < GATHER_B4) gather_slot(xb, ob, s2);
        int s3 = s + 512;
        if (s3 < GATHER_B4) gather_slot(xb, ob, s3);
    }
}

extern "C" void kernel_launch(void* const* d_in, const int* in_sizes, int n_in,
                              void* d_out, int out_size) {
    const float4* x = (const float4*)d_in[0];   // x (4, 32400, 256) f32
    float* out = (float*)d_out;
    fused_kernel<<<TOTAL_BLOCKS, 256>>>(x, out);
}